// round 16
// baseline (speedup 1.0000x reference)
#include <cuda_runtime.h>
#include <cuda_fp16.h>
#include <mma.h>
#include <math.h>

using namespace nvcuda;

#define NN   100000
#define EE   500000
#define TT   8
#define MSGD 64
#define HIDD 64
#define CC   16

typedef unsigned long long ull;

// ---------------------------------------------------------------------------
// Device scratch
// ---------------------------------------------------------------------------
__device__ __align__(16) float g_reduced[(size_t)NN * MSGD];
__device__ __align__(32) __half g_edge_h[TT * 64 * 64];   // fp16 edge matrices
__device__ int g_counts[TT];
__device__ int g_cursor[TT];
__device__ int g_src_s[EE];
__device__ int g_dst_s[EE];

// ---------------------------------------------------------------------------
// Packed fp32x2 helpers (Blackwell FFMA2)
// ---------------------------------------------------------------------------
__device__ __forceinline__ void fma2(ull& d, ull a, ull b) {
    asm volatile("fma.rn.f32x2 %0, %1, %2, %0;" : "+l"(d) : "l"(a), "l"(b));
}
__device__ __forceinline__ float2 asf2(ull v) {
    float2 r;
    asm("mov.b64 {%0, %1}, %2;" : "=f"(r.x), "=f"(r.y) : "l"(v));
    return r;
}
__device__ __forceinline__ float fast_sigmoid(float x) {
    return __fdividef(1.f, 1.f + __expf(-x));
}
__device__ __forceinline__ float fast_tanh(float x) {
    return 1.f - __fdividef(2.f, __expf(2.f * x) + 1.f);
}

// ---------------------------------------------------------------------------
// Kernel 0: zero reduction buffer + reset counters + pack edge mats to fp16.
// (wprep fused here so edge_gemm is the 4th launch -> ncu captures it)
// ---------------------------------------------------------------------------
__global__ void zero_kernel(const float* __restrict__ edge_emb) {
    int i = blockIdx.x * blockDim.x + threadIdx.x;
    if (i < NN * MSGD / 4) {
        reinterpret_cast<float4*>(g_reduced)[i] = make_float4(0.f, 0.f, 0.f, 0.f);
    }
    if (i < TT * 4096) g_edge_h[i] = __float2half_rn(edge_emb[i]);
    if (blockIdx.x == 0 && threadIdx.x < TT) {
        g_counts[threadIdx.x] = 0;
        g_cursor[threadIdx.x] = 0;
    }
}

// ---------------------------------------------------------------------------
// Kernel 1: per-block histogram of edge types
// ---------------------------------------------------------------------------
__global__ void hist_kernel(const int* __restrict__ etype) {
    __shared__ int h[TT];
    if (threadIdx.x < TT) h[threadIdx.x] = 0;
    __syncthreads();
    int e = blockIdx.x * blockDim.x + threadIdx.x;
    if (e < EE) atomicAdd(&h[etype[e]], 1);
    __syncthreads();
    if (threadIdx.x < TT) atomicAdd(&g_counts[threadIdx.x], h[threadIdx.x]);
}

// ---------------------------------------------------------------------------
// Kernel 2: bin edges by type
// ---------------------------------------------------------------------------
__global__ void scatter_kernel(const int* __restrict__ etype,
                               const int* __restrict__ src,
                               const int* __restrict__ dst) {
    __shared__ int h[TT], base[TT], h2[TT];
    int e = blockIdx.x * blockDim.x + threadIdx.x;
    if (threadIdx.x < TT) { h[threadIdx.x] = 0; h2[threadIdx.x] = 0; }
    __syncthreads();
    int t = 0, s = 0, d = 0;
    bool valid = (e < EE);
    if (valid) {
        t = etype[e]; s = src[e]; d = dst[e];
        atomicAdd(&h[t], 1);
    }
    __syncthreads();
    if (threadIdx.x < TT) {
        int b = 0;
#pragma unroll
        for (int q = 0; q < TT; q++) {
            int c = g_counts[q];
            if (q < (int)threadIdx.x) b += c;
        }
        base[threadIdx.x] = b + atomicAdd(&g_cursor[threadIdx.x], h[threadIdx.x]);
    }
    __syncthreads();
    if (valid) {
        int pos = base[t] + atomicAdd(&h2[t], 1);
        g_src_s[pos] = s;
        g_dst_s[pos] = d;
    }
}

// ---------------------------------------------------------------------------
// Kernel 3: edge messages via TENSOR CORES, 128-edge tiles, DYNAMIC smem.
// Block = 128 sorted edges (3907 blocks). Gather -> fp16 smem; 8 warps each
// own 16 rows x 64 cols (4 m16n16k16 acc frags); B frags from fp16 global
// (L1-warm); scatter sub-segment rows with red.v4. ~4 CTAs/SM (54KB smem).
// ---------------------------------------------------------------------------
#define ETILE 128
#define EGB ((EE + ETILE - 1) / ETILE)     // 3907
#define EGT 256
// layout: Xh half[ETILE*72] @0 (18432B), msgs float[ETILE*68] @18432 (34816B),
//         sdst int[ETILE] @53248 (512B) -> total 53760B
#define EDGE_SMEM (18432 + 34816 + 512)

__global__ void __launch_bounds__(EGT)
edge_gemm_kernel(const float* __restrict__ features) {
    extern __shared__ char esm[];
    __half* Xh   = (__half*)esm;                 // [edge_row][h], ldm 72
    float*  msgs = (float*)(esm + 18432);        // [edge_row][m], ldm 68
    int*    sdst = (int*)(esm + 53248);

    long e0 = (long)blockIdx.x * ETILE;
    long e1 = e0 + ETILE;
    if (e1 > EE) e1 = EE;
    int tid = threadIdx.x;
    int r = tid >> 1, p = tid & 1;         // 2 threads per edge row (32 floats each)

    int bases[TT + 1];
    {
        int b = 0;
#pragma unroll
        for (int t = 0; t < TT; t++) { bases[t] = b; b += g_counts[t]; }
        bases[TT] = b;
    }

    // ---- gather: row r <- features[src[e0+r]], fp16 convert ----
    {
        long e = e0 + r;
        __half2* dst = reinterpret_cast<__half2*>(Xh + r * 72 + p * 32);
        if (e < e1) {
            int s = g_src_s[e];
            if (p == 0) sdst[r] = g_dst_s[e];
            const float4* fp = reinterpret_cast<const float4*>(
                features + (size_t)s * 64 + p * 32);
#pragma unroll
            for (int i = 0; i < 8; i++) {
                float4 v = fp[i];
                dst[2 * i]     = __floats2half2_rn(v.x, v.y);
                dst[2 * i + 1] = __floats2half2_rn(v.z, v.w);
            }
        } else {
            __half2 z = __floats2half2_rn(0.f, 0.f);
#pragma unroll
            for (int i = 0; i < 16; i++) dst[i] = z;
        }
    }
    __syncthreads();

    int wid = tid >> 5;                     // 8 warps: rows [wid*16, wid*16+16)

    int t = 0;
    long s0 = e0;
    while (s0 < e1) {
        while (bases[t + 1] <= s0) t++;
        long send = (long)bases[t + 1] < e1 ? (long)bases[t + 1] : e1;

        // ---- GEMM with A_t over the whole tile (each warp: 16 x 64) ----
        {
            const __half* Bt = g_edge_h + (size_t)t * 4096;
            wmma::fragment<wmma::accumulator, 16, 16, 16, float> acc[4];
#pragma unroll
            for (int c = 0; c < 4; c++) wmma::fill_fragment(acc[c], 0.f);
#pragma unroll
            for (int k = 0; k < 4; k++) {
                wmma::fragment<wmma::matrix_a, 16, 16, 16, __half, wmma::row_major> a;
                wmma::load_matrix_sync(a, Xh + (wid * 16) * 72 + k * 16, 72);
#pragma unroll
                for (int c = 0; c < 4; c++) {
                    wmma::fragment<wmma::matrix_b, 16, 16, 16, __half, wmma::col_major> b;
                    wmma::load_matrix_sync(b, Bt + (c * 16) * 64 + k * 16, 64);
                    wmma::mma_sync(acc[c], a, b, acc[c]);
                }
            }
#pragma unroll
            for (int c = 0; c < 4; c++) {
                wmma::store_matrix_sync(msgs + (wid * 16) * 68 + c * 16, acc[c], 68,
                                        wmma::mem_row_major);
            }
        }
        __syncthreads();

        // ---- scatter rows belonging to [s0, send) ----
        {
            long e = e0 + r;
            if (e >= s0 && e < send) {
                int d = sdst[r];
                float* op = g_reduced + (size_t)d * 64 + p * 32;
                const float* mp = msgs + r * 68 + p * 32;
#pragma unroll
                for (int i = 0; i < 8; i++) {
                    asm volatile("red.global.add.v4.f32 [%0], {%1, %2, %3, %4};"
                                 :: "l"(op + i * 4),
                                    "f"(mp[i * 4]), "f"(mp[i * 4 + 1]),
                                    "f"(mp[i * 4 + 2]), "f"(mp[i * 4 + 3])
                                 : "memory");
                }
            }
        }
        s0 = send;
        if (s0 < e1) __syncthreads();  // only mixed-type tiles pay this barrier
    }
}

// ---------------------------------------------------------------------------
// Kernel 4: fused GRU + out projection — measured-best SIMT node (~166us).
// ---------------------------------------------------------------------------
#define NODE_SMEM (26000 * 4)
#define NBLOCKS 148
#define NTHREADS 256

__global__ void __launch_bounds__(NTHREADS, 1)
node_kernel(const float* __restrict__ features,
            const float* __restrict__ W_ih, const float* __restrict__ W_hh,
            const float* __restrict__ b_ih, const float* __restrict__ b_hh,
            const float* __restrict__ W_out, const float* __restrict__ b_out,
            float* __restrict__ out) {
    extern __shared__ float sm[];
    float* sWih  = sm;            // 12288
    float* sWhh  = sm + 12288;    // 12288
    float* sWoT  = sm + 24576;    // 1024 (W_out transposed [64][16])
    float* sbih  = sm + 25600;    // 192
    float* sbhh  = sm + 25792;    // 192
    float* sbout = sm + 25984;    // 16

    {
        float4* d1 = reinterpret_cast<float4*>(sWih);
        const float4* s1 = reinterpret_cast<const float4*>(W_ih);
        for (int i = threadIdx.x; i < 3072; i += blockDim.x) d1[i] = s1[i];
        float4* d2 = reinterpret_cast<float4*>(sWhh);
        const float4* s2 = reinterpret_cast<const float4*>(W_hh);
        for (int i = threadIdx.x; i < 3072; i += blockDim.x) d2[i] = s2[i];
        for (int i = threadIdx.x; i < CC * 64; i += blockDim.x) {
            int c = i / 64, j = i % 64;
            sWoT[j * CC + c] = W_out[i];
        }
        for (int i = threadIdx.x; i < 192; i += blockDim.x) {
            sbih[i] = b_ih[i];
            sbhh[i] = b_hh[i];
        }
        if (threadIdx.x < CC) sbout[threadIdx.x] = b_out[threadIdx.x];
    }
    __syncthreads();

    for (int n = blockIdx.x * NTHREADS + threadIdx.x; n < NN;
         n += NBLOCKS * NTHREADS) {

        ulonglong2 hh[16], rr[16];
        const ulonglong2* hp = reinterpret_cast<const ulonglong2*>(features + (size_t)n * 64);
        const ulonglong2* rp = reinterpret_cast<const ulonglong2*>(g_reduced + (size_t)n * 64);
#pragma unroll
        for (int q = 0; q < 16; q++) { hh[q] = hp[q]; rr[q] = rp[q]; }

        ull oacc[8];
        const ulonglong2* bo = reinterpret_cast<const ulonglong2*>(sbout);
#pragma unroll
        for (int i = 0; i < 4; i++) {
            ulonglong2 v = bo[i];
            oacc[2 * i] = v.x; oacc[2 * i + 1] = v.y;
        }

#pragma unroll 1
        for (int jq = 0; jq < 16; jq++) {
#pragma unroll
            for (int dj = 0; dj < 4; dj++) {
                int j = jq * 4 + dj;
                ull air = 0, aiz = 0, ain = 0, ahr = 0, ahz = 0, ahn = 0;
                const ulonglong2* wir = reinterpret_cast<const ulonglong2*>(sWih + (j      ) * 64);
                const ulonglong2* wiz = reinterpret_cast<const ulonglong2*>(sWih + (64  + j) * 64);
                const ulonglong2* win = reinterpret_cast<const ulonglong2*>(sWih + (128 + j) * 64);
                const ulonglong2* whr = reinterpret_cast<const ulonglong2*>(sWhh + (j      ) * 64);
                const ulonglong2* whz = reinterpret_cast<const ulonglong2*>(sWhh + (64  + j) * 64);
                const ulonglong2* whn = reinterpret_cast<const ulonglong2*>(sWhh + (128 + j) * 64);
#pragma unroll
                for (int q = 0; q < 16; q++) {
                    ulonglong2 rv = rr[q], hv = hh[q], wv;
                    wv = wir[q]; fma2(air, wv.x, rv.x); fma2(air, wv.y, rv.y);
                    wv = wiz[q]; fma2(aiz, wv.x, rv.x); fma2(aiz, wv.y, rv.y);
                    wv = win[q]; fma2(ain, wv.x, rv.x); fma2(ain, wv.y, rv.y);
                    wv = whr[q]; fma2(ahr, wv.x, hv.x); fma2(ahr, wv.y, hv.y);
                    wv = whz[q]; fma2(ahz, wv.x, hv.x); fma2(ahz, wv.y, hv.y);
                    wv = whn[q]; fma2(ahn, wv.x, hv.x); fma2(ahn, wv.y, hv.y);
                }
                float2 v;
                v = asf2(air); float ir  = v.x + v.y + sbih[j];
                v = asf2(aiz); float iz  = v.x + v.y + sbih[64 + j];
                v = asf2(ain); float inn = v.x + v.y + sbih[128 + j];
                v = asf2(ahr); float hr  = v.x + v.y + sbhh[j];
                v = asf2(ahz); float hz  = v.x + v.y + sbhh[64 + j];
                v = asf2(ahn); float hn  = v.x + v.y + sbhh[128 + j];
                float rg = fast_sigmoid(ir + hr);
                float zg = fast_sigmoid(iz + hz);
                float ng = fast_tanh(inn + rg * hn);
                float2 hjp = asf2((dj & 2) ? hh[jq].y : hh[jq].x);
                float hj = (dj & 1) ? hjp.y : hjp.x;
                float hnew = (1.f - zg) * ng + zg * hj;
                ull hn2;
                asm("mov.b64 %0, {%1, %1};" : "=l"(hn2) : "f"(hnew));
                const ulonglong2* wo = reinterpret_cast<const ulonglong2*>(sWoT + j * CC);
#pragma unroll
                for (int c = 0; c < 4; c++) {
                    ulonglong2 wv = wo[c];
                    fma2(oacc[2 * c], wv.x, hn2);
                    fma2(oacc[2 * c + 1], wv.y, hn2);
                }
            }
        }

        ulonglong2* op = reinterpret_cast<ulonglong2*>(out + (size_t)n * CC);
#pragma unroll
        for (int i = 0; i < 4; i++) {
            ulonglong2 v;
            v.x = oacc[2 * i]; v.y = oacc[2 * i + 1];
            op[i] = v;
        }
    }
}

// ---------------------------------------------------------------------------
extern "C" void kernel_launch(void* const* d_in, const int* in_sizes, int n_in,
                              void* d_out, int out_size) {
    const float* features = (const float*)d_in[0];
    const float* edge_emb = (const float*)d_in[1];
    const float* W_ih     = (const float*)d_in[2];
    const float* W_hh     = (const float*)d_in[3];
    const float* b_ih     = (const float*)d_in[4];
    const float* b_hh     = (const float*)d_in[5];
    const float* W_out    = (const float*)d_in[6];
    const float* b_out    = (const float*)d_in[7];
    const int*   etype    = (const int*)d_in[8];
    const int*   src      = (const int*)d_in[9];
    const int*   dst      = (const int*)d_in[10];
    float*       out      = (float*)d_out;

    cudaFuncSetAttribute(edge_gemm_kernel,
                         cudaFuncAttributeMaxDynamicSharedMemorySize, EDGE_SMEM);
    cudaFuncSetAttribute(node_kernel,
                         cudaFuncAttributeMaxDynamicSharedMemorySize, NODE_SMEM);

    zero_kernel<<<(NN * MSGD / 4 + 255) / 256, 256>>>(edge_emb);
    hist_kernel<<<(EE + 511) / 512, 512>>>(etype);
    scatter_kernel<<<(EE + 511) / 512, 512>>>(etype, src, dst);
    edge_gemm_kernel<<<EGB, EGT, EDGE_SMEM>>>(features);
    node_kernel<<<NBLOCKS, NTHREADS, NODE_SMEM>>>(features, W_ih, W_hh,
                                                  b_ih, b_hh, W_out, b_out, out);
}